// round 2
// baseline (speedup 1.0000x reference)
#include <cuda_runtime.h>
#include <math.h>

// Problem constants (fixed by setup_inputs)
#define B_  32
#define K_  16
#define T_  30
#define N_  128
#define n_  20
#define NN  (N_ * n_)        // 2560 nodes per batch
#define THREADS 512

#define YAW_THRESH  1.0471975511965976f   // pi/3
#define TWO_PI_F    6.28318530717958647692f

__device__ __forceinline__ float fast_sqrt(float x) {
    float r;
    asm("sqrt.approx.f32 %0, %1;" : "=f"(r) : "f"(x));
    return r;
}

// One block per batch b.
// Phase 1: build node table in smem: (x, y, yaw, 0). Masked nodes get x=+inf
//          (cost becomes +inf -> never wins the min, never triggers early exit).
//          No atomics, fixed order -> fully deterministic.
// Phase 2: one thread per (k, t). Scan nodes, keep running min, and exit as
//          soon as the min hits exactly 0 (cost >= 0 always, so the min is
//          finalized). Statistically ~25% of unmasked pairs cost exactly 0,
//          so expected scan length is ~8 nodes.
__global__ __launch_bounds__(THREADS, 1)
void consistency_fused(const float* __restrict__ preds,
                       const float* __restrict__ cn,
                       const int*   __restrict__ mask,
                       float* __restrict__ out) {
    const int b   = blockIdx.x;
    const int tid = threadIdx.x;

    __shared__ float4 s_nodes[NN];        // 40 KB
    __shared__ float  s_min[K_][T_];      // 1.9 KB

    // ---------------- Phase 1: node table ----------------
    const float2* cnb = (const float2*)cn + (size_t)b * NN;
    const int*    mb  = mask + (size_t)b * NN;

    for (int idx = tid; idx < NN; idx += THREADS) {
        int    m = mb[idx];
        float2 p = cnb[idx];
        float  x = p.x;
        float  yaw = 0.0f;
        if (m == 1) {
            x = __int_as_float(0x7f800000);   // +inf
        } else if (idx % n_ != 0) {
            float2 q = cnb[idx - 1];
            yaw = -atan2f(p.x - q.x, p.y - q.y);
        }
        s_nodes[idx] = make_float4(x, p.y, yaw, 0.0f);
    }
    __syncthreads();

    // ---------------- Phase 2: per-(k,t) min with early exit ----------------
    if (tid < K_ * T_) {
        const int k = tid / T_;
        const int t = tid - k * T_;

        const float2* pp = (const float2*)preds + ((size_t)b * K_ + k) * T_;
        const float2  pt = pp[t];
        float pyaw = 0.0f;
        if (t != 0) {
            float2 pm = pp[t - 1];
            pyaw = -atan2f(pt.x - pm.x, pt.y - pm.y);
        }

        float mymin = __int_as_float(0x7f800000);   // +inf
        for (int j = 0; j < NN; ++j) {
            float4 nd = s_nodes[j];
            float dx = nd.x - pt.x;
            float dy = nd.y - pt.y;
            float d2 = fmaf(dx, dx, dy * dy);

            float a = fabsf(nd.z - pyaw);
            a = fminf(a, TWO_PI_F - a);
            float c = fmaxf(a - YAW_THRESH, 0.0f);

            // exact-zero semantics: dist cost is 0 iff d2 <= 4
            float cd = (d2 <= 4.0f) ? 0.0f : (fast_sqrt(d2) - 2.0f);
            c += cd;

            mymin = fminf(mymin, c);
            if (mymin == 0.0f) break;   // min finalized (cost >= 0 always)
        }
        s_min[k][t] = mymin;
    }
    __syncthreads();

    // ---------------- Reduction: sum over T per k (deterministic order) ----
    if (tid < K_) {
        float s = 0.0f;
        #pragma unroll
        for (int t = 0; t < T_; ++t) s += s_min[tid][t];
        out[b * K_ + tid] = s;
    }
}

extern "C" void kernel_launch(void* const* d_in, const int* in_sizes, int n_in,
                              void* d_out, int out_size) {
    const float* preds = (const float*)d_in[0];
    const float* cn    = (const float*)d_in[1];
    const int*   mask  = (const int*)d_in[2];
    float* out = (float*)d_out;

    consistency_fused<<<B_, THREADS>>>(preds, cn, mask, out);
}

// round 3
// speedup vs baseline: 4.6396x; 4.6396x over previous
#include <cuda_runtime.h>
#include <math.h>

// Problem constants (fixed by setup_inputs)
#define B_  32
#define K_  16
#define T_  30
#define N_  128
#define n_  20
#define NN  (N_ * n_)        // 2560 nodes per batch

#define YAW_THRESH  1.0471975511965976f   // pi/3
#define INF_F       __int_as_float(0x7f800000)

__device__ __forceinline__ float fast_sqrt(float x) {
    float r;
    asm("sqrt.approx.f32 %0, %1;" : "=f"(r) : "f"(x));
    return r;
}

// One block per (b, k). 256 threads = 8 warps.
// Phase 1: build node table in smem: (x | +inf if masked, y, ux, uy) where
//          (ux,uy) is the raw direction vector (prev -> cur), or (0,1) at
//          centerline starts (yaw = 0 maps to direction (0,1) under
//          theta = -atan2(ux, uy); the reflection preserves |angle diffs|).
// Phase 2: warp w handles timesteps t = w, w+8, ... Each chunk of 32 nodes is
//          tested lane-parallel for exact-zero cost:
//              d2 <= 4  AND  dot >= 0  AND  cross^2 <= 3*dot^2
//          (tan(pi/3)^2 == 3). Any hit -> min is 0, warp exits (cost >= 0).
//          Only zero-free chunks pay the atan2 cost path.
__global__ __launch_bounds__(256)
void consistency_kernel(const float* __restrict__ preds,
                        const float* __restrict__ cn,
                        const int*   __restrict__ mask,
                        float* __restrict__ out) {
    const int bk = blockIdx.x;
    const int b  = bk >> 4;               // / K_

    __shared__ float4 s_nodes[NN];        // 40 KB
    __shared__ float  s_min[32];

    const int tid = threadIdx.x;

    // ---------------- Phase 1: per-batch node table ----------------
    const float2* cnb = (const float2*)cn + (size_t)b * NN;
    const int*    mb  = mask + (size_t)b * NN;

    #pragma unroll
    for (int i = 0; i < NN / 256; ++i) {
        const int idx = tid + i * 256;
        float2 p = cnb[idx];
        int    m = mb[idx];
        float ux = 0.0f, uy = 1.0f;       // yaw 0 <-> direction (0, 1)
        if (idx % n_ != 0) {
            float2 q = cnb[idx - 1];
            ux = p.x - q.x;
            uy = p.y - q.y;
        }
        float x = (m == 1) ? INF_F : p.x; // masked -> dist cost = +inf
        s_nodes[idx] = make_float4(x, p.y, ux, uy);
    }
    __syncthreads();

    // ---------------- Phase 2: warp-per-timestep scan ----------------
    const int warp = tid >> 5;
    const int lane = tid & 31;
    const float2* pp = (const float2*)preds + (size_t)bk * T_;

    for (int t = warp; t < T_; t += 8) {
        const float2 pt = pp[t];
        float vx = 0.0f, vy = 1.0f;
        if (t != 0) {
            float2 pm = pp[t - 1];
            vx = pt.x - pm.x;
            vy = pt.y - pm.y;
        }

        float lmin = INF_F;
        for (int base = 0; base < NN; base += 32) {
            float4 nd = s_nodes[base + lane];
            float dx = nd.x - pt.x;
            float dy = nd.y - pt.y;
            float d2 = fmaf(dx, dx, dy * dy);

            float dt = fmaf(nd.z, vx, nd.w * vy);   // dot(u, v)
            float cr = fmaf(nd.z, vy, -nd.w * vx);  // cross(u, v)

            bool zero = (d2 <= 4.0f) && (dt >= 0.0f) &&
                        (cr * cr <= 3.0f * dt * dt);
            if (__ballot_sync(0xffffffffu, zero)) { lmin = 0.0f; break; }

            // no zero in this chunk: compute the actual costs
            float cd = (d2 <= 4.0f) ? 0.0f : (fast_sqrt(d2) - 2.0f);
            float a  = atan2f(fabsf(cr), dt);       // |wrapped yaw diff|
            float c  = cd + fmaxf(a - YAW_THRESH, 0.0f);
            lmin = fminf(lmin, c);
        }

        lmin = fminf(lmin, __shfl_xor_sync(0xffffffffu, lmin, 16));
        lmin = fminf(lmin, __shfl_xor_sync(0xffffffffu, lmin, 8));
        lmin = fminf(lmin, __shfl_xor_sync(0xffffffffu, lmin, 4));
        lmin = fminf(lmin, __shfl_xor_sync(0xffffffffu, lmin, 2));
        lmin = fminf(lmin, __shfl_xor_sync(0xffffffffu, lmin, 1));
        if (lane == 0) s_min[t] = lmin;
    }
    __syncthreads();

    // ---------------- Sum over T (deterministic shfl tree) ----------------
    if (tid < 32) {
        float v = (tid < T_) ? s_min[tid] : 0.0f;
        v += __shfl_xor_sync(0xffffffffu, v, 16);
        v += __shfl_xor_sync(0xffffffffu, v, 8);
        v += __shfl_xor_sync(0xffffffffu, v, 4);
        v += __shfl_xor_sync(0xffffffffu, v, 2);
        v += __shfl_xor_sync(0xffffffffu, v, 1);
        if (tid == 0) out[bk] = v;
    }
}

extern "C" void kernel_launch(void* const* d_in, const int* in_sizes, int n_in,
                              void* d_out, int out_size) {
    const float* preds = (const float*)d_in[0];
    const float* cn    = (const float*)d_in[1];
    const int*   mask  = (const int*)d_in[2];
    float* out = (float*)d_out;

    consistency_kernel<<<B_ * K_, 256>>>(preds, cn, mask, out);
}